// round 10
// baseline (speedup 1.0000x reference)
#include <cuda_runtime.h>
#include <cuda_fp16.h>
#include <cstdint>

// ---------------- problem constants ----------------
#define OUTF  11008
#define INF   4096
#define BATCH 64
#define NG    32              // 4096/128 quant groups
#define MTILE 32              // weight rows per CTA
#define KC    64              // K per chunk
#define NCHUNK 64
#define NBLK  (OUTF / MTILE)  // 344 CTAs

// rings
#define NX    6               // X slots (8KB each)
#define NW    4               // W raw slots
#define SPREF 4               // prefetch distance, wait_group(SPREF-1)
#define WROW  272             // padded raw W row stride (bank-conflict-free)

// smem layout from 1KB-aligned base
#define SC_OFF  0                            // 2KB scales (32 rows x 32 groups fp16)
#define X_OFF   2048                         // 6 x 8192 = 49152
#define WR_OFF  (X_OFF + NX * 8192)          // 51200; 4 x 8704 = 34816
#define WF_OFF  (WR_OFF + NW * MTILE * WROW) // 86016; 2 x 4096
#define SMEM_GEMM (WF_OFF + 2 * 4096 + 1024) // 95232  (x2 CTAs = 190464 < 228KB)

// ---------------- device globals ----------------
__device__ __half2 g_x16[BATCH * INF / 2];
__device__ __half  g_sc16[OUTF * NG];
__device__ float   g_badd[OUTF];

// ---------------- helpers ----------------
static __device__ __forceinline__ uint32_t smem_u32(const void* p) {
    uint32_t a;
    asm("{ .reg .u64 t; cvta.to.shared.u64 t, %1; cvt.u32.u64 %0, t; }" : "=r"(a) : "l"(p));
    return a;
}
static __device__ __forceinline__ uint32_t swz(uint32_t off) {
    return off ^ ((off >> 3) & 0x70);
}
static __device__ __forceinline__ void cpa16(uint32_t dst, const void* src) {
    asm volatile("cp.async.cg.shared.global [%0], [%1], 16;" :: "r"(dst), "l"(src));
}
static __device__ __forceinline__ void cpa_commit() {
    asm volatile("cp.async.commit_group;" ::: "memory");
}
static __device__ __forceinline__ void ldsm4(uint32_t* r, uint32_t addr) {
    asm volatile("ldmatrix.sync.aligned.m8n8.x4.shared.b16 {%0,%1,%2,%3}, [%4];"
        : "=r"(r[0]), "=r"(r[1]), "=r"(r[2]), "=r"(r[3]) : "r"(addr));
}
static __device__ __forceinline__ void mma16816(float* d, const uint32_t* a,
                                                uint32_t b0, uint32_t b1) {
    asm volatile("mma.sync.aligned.m16n8k16.row.col.f32.f16.f16.f32 "
        "{%0,%1,%2,%3}, {%4,%5,%6,%7}, {%8,%9}, {%0,%1,%2,%3};"
        : "+f"(d[0]), "+f"(d[1]), "+f"(d[2]), "+f"(d[3])
        : "r"(a[0]), "r"(a[1]), "r"(a[2]), "r"(a[3]), "r"(b0), "r"(b1));
}
static __device__ __forceinline__ __half2 u32_as_h2(uint32_t u) {
    __half2 h; *reinterpret_cast<uint32_t*>(&h) = u; return h;
}
static __device__ __forceinline__ uint32_t h2_as_u32(__half2 h) {
    return *reinterpret_cast<uint32_t*>(&h);
}

#define LDS128(r0, r1, r2, r3, addr) \
    asm volatile("ld.shared.v4.u32 {%0, %1, %2, %3}, [%4];" \
        : "=r"(r0), "=r"(r1), "=r"(r2), "=r"(r3) : "r"(addr))
#define LDS64(r0, r1, addr) \
    asm volatile("ld.shared.v2.u32 {%0, %1}, [%2];" \
        : "=r"(r0), "=r"(r1) : "r"(addr))
#define STS128(addr, r0, r1, r2, r3) \
    asm volatile("st.shared.v4.b32 [%0], {%1, %2, %3, %4};" \
        :: "r"(addr), "r"(r0), "r"(r1), "r"(r2), "r"(r3) : "memory")

// 4 int8 bytes (packed u32) -> 2 half2, times s2 (exact PRMT 0x6400 trick)
static __device__ __forceinline__ void dq4(uint32_t packed, __half2 s2, __half2 c1152,
                                           uint32_t& o0, uint32_t& o1) {
    uint32_t v  = packed ^ 0x80808080u;
    uint32_t lo = __byte_perm(v, 0x64646464u, 0x4140);
    uint32_t hi = __byte_perm(v, 0x64646464u, 0x4342);
    o0 = h2_as_u32(__hmul2(__hsub2(u32_as_h2(lo), c1152), s2));
    o1 = h2_as_u32(__hmul2(__hsub2(u32_as_h2(hi), c1152), s2));
}

static __device__ __forceinline__ float read_mode16(const void* p, int i, int mode) {
    if (mode == 1) {
        unsigned short u = reinterpret_cast<const unsigned short*>(p)[i];
        return __uint_as_float(((unsigned)u) << 16);
    } else if (mode == 0) {
        return __half2float(reinterpret_cast<const __half*>(p)[i]);
    }
    return reinterpret_cast<const float*>(p)[i];
}

// ---------------- fused prolog: x->fp16, scale->fp16, bias+res->f32 ----------------
__global__ void prolog_kernel(const float* __restrict__ x,
                              const void* __restrict__ s,
                              const void* __restrict__ b,
                              const void* __restrict__ r) {
    const int idx = blockIdx.x * 256 + threadIdx.x;   // 512*256 = 131072

    float2 v = reinterpret_cast<const float2*>(x)[idx];
    g_x16[idx] = __floats2half2_rn(v.x, v.y);

    // per-block scale dtype detection (256B, L2-resident after first block)
    bool bf = true, fh = true;
    const unsigned* su = (const unsigned*)s;
    #pragma unroll 8
    for (int i = 0; i < 64; i++) {
        unsigned w = su[i];
        #pragma unroll
        for (int h = 0; h < 2; h++) {
            unsigned u = (h ? (w >> 16) : w) & 0xFFFFu;
            float ab = __uint_as_float(u << 16);
            float af = __half2float(__ushort_as_half((unsigned short)u));
            bf &= (ab > 5e-5f && ab < 0.02f);
            fh &= (af > 5e-5f && af < 0.02f);
        }
    }
    const int m = bf ? 1 : (fh ? 0 : 2);

    for (int i = idx; i < OUTF * NG; i += 512 * 256)
        g_sc16[i] = __float2half(read_mode16(s, i, m));
    if (idx < OUTF)
        g_badd[idx] = read_mode16(b, idx, m) + read_mode16(r, idx, m);
}

// ---------------- unified GEMM body (WMODE: 1 = int32 weights, 0 = int8) --------
template <int WMODE>
static __device__ __forceinline__ void gemm_body(const char* __restrict__ Wb,
                                                 float* __restrict__ out) {
    extern __shared__ char smem_raw[];
    uint32_t sb = (smem_u32(smem_raw) + 1023) & ~1023u;
    const int tid = threadIdx.x, lane = tid & 31, wid = tid >> 5;
    const int mr = wid & 1, nc = wid >> 1;     // 2 row-groups(16) x 4 col-groups(16)
    const int t = lane >> 3;
    const int row0 = blockIdx.x * MTILE;
    const char* xb = (const char*)g_x16;
    const uint32_t SC = sb, X0 = sb + X_OFF, WR = sb + WR_OFF, WFP = sb + WF_OFF;

    auto issueX = [&](int p, int slot) {
        uint32_t xsl = X0 + slot * 8192;
        const int k0 = p * KC;
        #pragma unroll
        for (int j = 0; j < 2; j++) {
            int c = tid + j * 256, r = c >> 3, q = c & 7;
            cpa16(xsl + swz(r * 128 + q * 16),
                  xb + (size_t)r * (INF * 2) + (size_t)k0 * 2 + q * 16);
        }
    };
    auto issueW = [&](int p, int slot) {
        uint32_t wsl = WR + slot * (MTILE * WROW);
        const int k0 = p * KC;
        if (WMODE) {
            #pragma unroll
            for (int j = 0; j < 2; j++) {      // 32 rows x 256B = 8KB
                int c = tid + j * 256, r = c >> 4, q = c & 15;
                cpa16(wsl + r * WROW + q * 16,
                      Wb + ((size_t)(row0 + r) * INF + k0 + q * 4) * 4);
            }
        } else {
            if (tid < 128) {                   // 32 rows x 64B = 2KB
                int r = tid >> 2, q = tid & 3;
                cpa16(wsl + r * WROW + q * 16,
                      Wb + (size_t)(row0 + r) * INF + k0 + q * 16);
            }
        }
    };

    {   // prologue: scales + chunks 0..SPREF-1
        const char* scb = (const char*)g_sc16 + (size_t)row0 * NG * 2;
        if (tid < 128) cpa16(SC + tid * 16, scb + tid * 16);   // 2KB
        issueX(0, 0); issueW(0, 0); cpa_commit();
        issueX(1, 1); issueW(1, 1); cpa_commit();
        issueX(2, 2); issueW(2, 2); cpa_commit();
        issueX(3, 3); issueW(3, 3); cpa_commit();
    }

    const __half2 c1152 = __half2half2(__ushort_as_half((unsigned short)0x6480));
    float acc[2][4] = {};
    const int rr = tid & 31, hh = tid >> 5;    // dequant: row rr, eighth hh (8 vals)
    int x6 = 0, w4 = 0;                         // i % 6, i % 4

    for (int i = 0; i < NCHUNK; i++) {
        asm volatile("cp.async.wait_group %0;" :: "n"(SPREF - 1) : "memory");
        __syncthreads();                        // chunk i (X + W raw) visible

        const uint32_t xsl = X0 + x6 * 8192;
        const uint32_t wsl = WR + w4 * (MTILE * WROW);
        const uint32_t wfp = WFP + (i & 1) * 4096;

        // ---- B fragments (16 cols per warp) ----
        uint32_t bfr[4][4];
        #pragma unroll
        for (int kt = 0; kt < 4; kt++) {
            int n  = nc * 16 + ((t >> 1) << 3) + (lane & 7);
            int cb = kt * 32 + ((t & 1) << 4);
            ldsm4(bfr[kt], xsl + swz(n * 128 + cb));
        }

        // ---- dequant raw W -> Wfp (8 values per thread) ----
        {
            const int g = i >> 1;
            unsigned short sv;
            asm volatile("ld.shared.u16 %0, [%1];" : "=h"(sv)
                : "r"(SC + (uint32_t)(rr * NG + g) * 2) : "memory");
            __half2 s2 = __half2half2(__ushort_as_half(sv));
            uint32_t o[4];
            if (WMODE) {
                #pragma unroll
                for (int k = 0; k < 2; k++) {
                    uint32_t a0, a1, a2, a3;
                    LDS128(a0, a1, a2, a3, wsl + rr * WROW + hh * 32 + k * 16);
                    uint32_t t01 = __byte_perm(a0, a1, 0x0040);
                    uint32_t t23 = __byte_perm(a2, a3, 0x0040);
                    dq4(__byte_perm(t01, t23, 0x5410), s2, c1152, o[2*k], o[2*k+1]);
                }
            } else {
                uint32_t a0, a1;
                LDS64(a0, a1, wsl + rr * WROW + hh * 8);
                dq4(a0, s2, c1152, o[0], o[1]);
                dq4(a1, s2, c1152, o[2], o[3]);
            }
            STS128(wfp + swz((uint32_t)rr * 128 + (uint32_t)hh * 16),
                   o[0], o[1], o[2], o[3]);
        }

        __syncthreads();   // all reads of chunk-i slots done; Wfp visible

        // ---- prefetch chunk i+SPREF (W slot w4 now fully consumed) ----
        if (i + SPREF < NCHUNK) {
            int xs = x6 + SPREF; if (xs >= NX) xs -= NX;
            issueX(i + SPREF, xs);
            issueW(i + SPREF, w4);
        }
        cpa_commit();

        // ---- A fragments + MMA ----
        #pragma unroll
        for (int kt = 0; kt < 4; kt++) {
            uint32_t afr[4];
            int row = mr * 16 + ((t & 1) << 3) + (lane & 7);
            int cb  = kt * 32 + ((t >> 1) << 4);
            ldsm4(afr, wfp + swz(row * 128 + cb));
            #pragma unroll
            for (int nt = 0; nt < 2; nt++)
                mma16816(acc[nt], afr, bfr[kt][nt * 2], bfr[kt][nt * 2 + 1]);
        }

        x6 = (x6 == NX - 1) ? 0 : x6 + 1;
        w4 = (w4 == NW - 1) ? 0 : w4 + 1;
    }

    // ---- epilogue ----
    const int o0 = row0 + mr * 16 + (lane >> 2);
    float b0 = g_badd[o0], b8 = g_badd[o0 + 8];
    #pragma unroll
    for (int nt = 0; nt < 2; nt++) {
        int bc = nc * 16 + nt * 8 + (lane & 3) * 2;
        out[(size_t)bc * OUTF + o0]           = acc[nt][0] + b0;
        out[(size_t)(bc + 1) * OUTF + o0]     = acc[nt][1] + b0;
        out[(size_t)bc * OUTF + o0 + 8]       = acc[nt][2] + b8;
        out[(size_t)(bc + 1) * OUTF + o0 + 8] = acc[nt][3] + b8;
    }
}

__global__ void __launch_bounds__(256, 2)
gemm_kernel(const void* __restrict__ Wv, float* __restrict__ out) {
    const int* wi = (const int*)Wv;           // uniform dtype check on 256B of W
    bool i32 = true;
    #pragma unroll 8
    for (int i = 0; i < 64; i++) { int q = wi[i]; i32 &= (q >= -127 && q <= 127); }
    if (i32) gemm_body<1>((const char*)Wv, out);
    else     gemm_body<0>((const char*)Wv, out);
}

// ---------------- launch ----------------
extern "C" void kernel_launch(void* const* d_in, const int* in_sizes, int n_in,
                              void* d_out, int out_size) {
    const void* x = nullptr; const void* wq = nullptr; const void* scale = nullptr;
    const void* bias = nullptr; const void* wres = nullptr;
    for (int i = 0; i < n_in; i++) {
        long long n = in_sizes[i];
        if (n == (long long)BATCH * INF)     x = d_in[i];
        else if (n == (long long)OUTF * INF) wq = d_in[i];
        else if (n == (long long)OUTF * NG)  scale = d_in[i];
        else if (n == OUTF) { if (!bias) bias = d_in[i]; else wres = d_in[i]; }
    }
    if (!x || !wq || !scale || !bias || !wres) {
        if (n_in >= 5) {
            x = d_in[0]; wq = d_in[1]; scale = d_in[2]; bias = d_in[3]; wres = d_in[4];
        } else return;
    }
    float* out = (float*)d_out;

    prolog_kernel<<<512, 256>>>((const float*)x, scale, bias, wres);

    (void)cudaFuncSetAttribute(gemm_kernel,
                               cudaFuncAttributeMaxDynamicSharedMemorySize, SMEM_GEMM);
    gemm_kernel<<<NBLK, 256, SMEM_GEMM>>>(wq, out);
}

// round 11
// speedup vs baseline: 1.0654x; 1.0654x over previous
#include <cuda_runtime.h>
#include <cuda_fp16.h>
#include <cstdint>

// ---------------- problem constants ----------------
#define OUTF  11008
#define INF   4096
#define BATCH 64
#define NG    32              // 4096/128 quant groups
#define MTILE 32              // weight rows per CTA
#define KC    128             // K per chunk == one quant group
#define NCHUNK 32
#define NBLK  (OUTF / MTILE)  // 344 CTAs

#define SPREF 2               // prefetch distance; wait_group(1)
#define WROW  528             // padded raw int32 W row stride (conflict-free)

// smem from 1KB-aligned base:
//   SC:  2KB scales (32 rows x 32 groups fp16)
//   X:   2 slots x 16KB  (each: 2 sub-tiles of 64 rows x 128B, SW128)
//   WR:  2 slots x 16896 (32 rows x 528B padded raw int32)
//   WFP: 2 bufs  x 8KB   (each: 2 sub-tiles of 32 rows x 128B fp16, SW128)
#define SC_OFF  0
#define X_OFF   2048
#define WR_OFF  (X_OFF + 2 * 16384)          // 34816
#define WF_OFF  (WR_OFF + 2 * (MTILE * WROW))// 68608
#define SMEM_GEMM (WF_OFF + 2 * 8192 + 1024) // 86016 (x2 CTAs = 172KB < 227KB)

// ---------------- device globals ----------------
__device__ __half2 g_x16[BATCH * INF / 2];
__device__ __half  g_sc16[OUTF * NG];
__device__ float   g_badd[OUTF];

// ---------------- helpers ----------------
static __device__ __forceinline__ uint32_t smem_u32(const void* p) {
    uint32_t a;
    asm("{ .reg .u64 t; cvta.to.shared.u64 t, %1; cvt.u32.u64 %0, t; }" : "=r"(a) : "l"(p));
    return a;
}
static __device__ __forceinline__ uint32_t swz(uint32_t off) {
    return off ^ ((off >> 3) & 0x70);
}
static __device__ __forceinline__ void cpa16(uint32_t dst, const void* src) {
    asm volatile("cp.async.cg.shared.global [%0], [%1], 16;" :: "r"(dst), "l"(src));
}
static __device__ __forceinline__ void cpa_commit() {
    asm volatile("cp.async.commit_group;" ::: "memory");
}
static __device__ __forceinline__ void ldsm4(uint32_t* r, uint32_t addr) {
    asm volatile("ldmatrix.sync.aligned.m8n8.x4.shared.b16 {%0,%1,%2,%3}, [%4];"
        : "=r"(r[0]), "=r"(r[1]), "=r"(r[2]), "=r"(r[3]) : "r"(addr));
}
static __device__ __forceinline__ void mma16816(float* d, const uint32_t* a,
                                                uint32_t b0, uint32_t b1) {
    asm volatile("mma.sync.aligned.m16n8k16.row.col.f32.f16.f16.f32 "
        "{%0,%1,%2,%3}, {%4,%5,%6,%7}, {%8,%9}, {%0,%1,%2,%3};"
        : "+f"(d[0]), "+f"(d[1]), "+f"(d[2]), "+f"(d[3])
        : "r"(a[0]), "r"(a[1]), "r"(a[2]), "r"(a[3]), "r"(b0), "r"(b1));
}
static __device__ __forceinline__ __half2 u32_as_h2(uint32_t u) {
    __half2 h; *reinterpret_cast<uint32_t*>(&h) = u; return h;
}
static __device__ __forceinline__ uint32_t h2_as_u32(__half2 h) {
    return *reinterpret_cast<uint32_t*>(&h);
}

#define LDS128(r0, r1, r2, r3, addr) \
    asm volatile("ld.shared.v4.u32 {%0, %1, %2, %3}, [%4];" \
        : "=r"(r0), "=r"(r1), "=r"(r2), "=r"(r3) : "r"(addr))
#define STS128(addr, r0, r1, r2, r3) \
    asm volatile("st.shared.v4.b32 [%0], {%1, %2, %3, %4};" \
        :: "r"(addr), "r"(r0), "r"(r1), "r"(r2), "r"(r3) : "memory")

// 4 int8 bytes (packed u32) -> 2 half2, times s2 (exact PRMT 0x6400 trick)
static __device__ __forceinline__ void dq4(uint32_t packed, __half2 s2, __half2 c1152,
                                           uint32_t& o0, uint32_t& o1) {
    uint32_t v  = packed ^ 0x80808080u;
    uint32_t lo = __byte_perm(v, 0x64646464u, 0x4140);
    uint32_t hi = __byte_perm(v, 0x64646464u, 0x4342);
    o0 = h2_as_u32(__hmul2(__hsub2(u32_as_h2(lo), c1152), s2));
    o1 = h2_as_u32(__hmul2(__hsub2(u32_as_h2(hi), c1152), s2));
}

static __device__ __forceinline__ float read_mode16(const void* p, int i, int mode) {
    if (mode == 1) {
        unsigned short u = reinterpret_cast<const unsigned short*>(p)[i];
        return __uint_as_float(((unsigned)u) << 16);
    } else if (mode == 0) {
        return __half2float(reinterpret_cast<const __half*>(p)[i]);
    }
    return reinterpret_cast<const float*>(p)[i];
}

// ---------------- fused prolog: x->fp16, scale->fp16, bias+res->f32 ----------------
__global__ void prolog_kernel(const float* __restrict__ x,
                              const void* __restrict__ s,
                              const void* __restrict__ b,
                              const void* __restrict__ r) {
    const int idx = blockIdx.x * 256 + threadIdx.x;   // 512*256 = 131072

    float2 v = reinterpret_cast<const float2*>(x)[idx];
    g_x16[idx] = __floats2half2_rn(v.x, v.y);

    bool bf = true, fh = true;
    const unsigned* su = (const unsigned*)s;
    #pragma unroll 8
    for (int i = 0; i < 64; i++) {
        unsigned w = su[i];
        #pragma unroll
        for (int h = 0; h < 2; h++) {
            unsigned u = (h ? (w >> 16) : w) & 0xFFFFu;
            float ab = __uint_as_float(u << 16);
            float af = __half2float(__ushort_as_half((unsigned short)u));
            bf &= (ab > 5e-5f && ab < 0.02f);
            fh &= (af > 5e-5f && af < 0.02f);
        }
    }
    const int m = bf ? 1 : (fh ? 0 : 2);

    for (int i = idx; i < OUTF * NG; i += 512 * 256)
        g_sc16[i] = __float2half(read_mode16(s, i, m));
    if (idx < OUTF)
        g_badd[idx] = read_mode16(b, idx, m) + read_mode16(r, idx, m);
}

// ---------------- unified GEMM body (WMODE: 1 = int32 weights, 0 = int8) --------
template <int WMODE>
static __device__ __forceinline__ void gemm_body(const char* __restrict__ Wb,
                                                 float* __restrict__ out) {
    extern __shared__ char smem_raw[];
    uint32_t sb = (smem_u32(smem_raw) + 1023) & ~1023u;
    const int tid = threadIdx.x, lane = tid & 31, wid = tid >> 5;
    const int mr = wid & 1, nc = wid >> 1;     // warp tile: 16 rows x 16 cols
    const int t = lane >> 3;
    const int row0 = blockIdx.x * MTILE;
    const char* xb = (const char*)g_x16;
    const uint32_t SC = sb, X0 = sb + X_OFF, WR = sb + WR_OFF, WFP = sb + WF_OFF;

    // X chunk: 16KB = 2 sub-tiles (K halves) of 64 rows x 128B, SW128
    auto issueX = [&](int p, int slot) {
        uint32_t xsl = X0 + slot * 16384;
        const int k0b = p * KC * 2;            // byte offset in X row
        #pragma unroll
        for (int j = 0; j < 4; j++) {          // 1024 x 16B
            int c = tid + j * 256;
            int sub = c >> 9, r = (c >> 3) & 63, q = c & 7;
            cpa16(xsl + sub * 8192 + swz(r * 128 + q * 16),
                  xb + (size_t)r * (INF * 2) + k0b + sub * 128 + q * 16);
        }
    };
    // W chunk: int32 -> 32 rows x 512B (padded rows); int8 -> 32 rows x 128B
    auto issueW = [&](int p, int slot) {
        uint32_t wsl = WR + slot * (MTILE * WROW);
        const int k0 = p * KC;
        if (WMODE) {
            #pragma unroll
            for (int j = 0; j < 4; j++) {      // 1024 x 16B = 16KB
                int c = tid + j * 256, r = c >> 5, q = c & 31;
                cpa16(wsl + r * WROW + q * 16,
                      Wb + ((size_t)(row0 + r) * INF + k0 + q * 4) * 4);
            }
        } else {                                // 256 x 16B = 4KB
            int r = tid >> 3, q = tid & 7;
            cpa16(wsl + r * WROW + q * 16,
                  Wb + (size_t)(row0 + r) * INF + k0 + q * 16);
        }
    };

    {   // prologue: scales (in group 0) + chunks 0,1
        const char* scb = (const char*)g_sc16 + (size_t)row0 * NG * 2;
        if (tid < 128) cpa16(SC + tid * 16, scb + tid * 16);   // 2KB
        issueX(0, 0); issueW(0, 0); cpa_commit();              // g0
        issueX(1, 1); issueW(1, 1); cpa_commit();              // g1
    }

    const __half2 c1152 = __half2half2(__ushort_as_half((unsigned short)0x6480));
    float acc[2][4] = {};
    const int rr = tid & 31, hh = tid >> 5;    // dequant: row rr, 16-val segment hh

    for (int i = 0; i < NCHUNK; i++) {
        // g_k = {X_k, W_k}; at iter i committed through g_{i+1}; keep <=1 pending
        asm volatile("cp.async.wait_group 1;" ::: "memory");
        __syncthreads();                        // barrier 1: chunk i visible

        const uint32_t xsl = X0 + (i & 1) * 16384;
        const uint32_t wsl = WR + (i & 1) * (MTILE * WROW);
        const uint32_t wfp = WFP + (i & 1) * 8192;

        // ---- B fragments: 8 K16-tiles x 16 cols ----
        uint32_t bfr[8][4];
        #pragma unroll
        for (int kt = 0; kt < 8; kt++) {
            int sub = kt >> 2;
            int n   = nc * 16 + ((t >> 1) << 3) + (lane & 7);
            int cb  = (kt & 3) * 32 + ((t & 1) << 4);
            ldsm4(bfr[kt], xsl + sub * 8192 + swz(n * 128 + cb));
        }

        // ---- dequant raw W -> Wfp (16 fp16 per thread) ----
        {
            unsigned short sv;                 // group g == i (KC == group size)
            asm volatile("ld.shared.u16 %0, [%1];" : "=h"(sv)
                : "r"(SC + (uint32_t)(rr * NG + i) * 2) : "memory");
            __half2 s2 = __half2half2(__ushort_as_half(sv));
            uint32_t o[8];
            if (WMODE) {
                #pragma unroll
                for (int k = 0; k < 4; k++) {
                    uint32_t a0, a1, a2, a3;
                    LDS128(a0, a1, a2, a3, wsl + rr * WROW + hh * 64 + k * 16);
                    uint32_t t01 = __byte_perm(a0, a1, 0x0040);
                    uint32_t t23 = __byte_perm(a2, a3, 0x0040);
                    dq4(__byte_perm(t01, t23, 0x5410), s2, c1152, o[2*k], o[2*k+1]);
                }
            } else {
                uint32_t a0, a1, a2, a3;
                LDS128(a0, a1, a2, a3, wsl + rr * WROW + hh * 16);
                dq4(a0, s2, c1152, o[0], o[1]);
                dq4(a1, s2, c1152, o[2], o[3]);
                dq4(a2, s2, c1152, o[4], o[5]);
                dq4(a3, s2, c1152, o[6], o[7]);
            }
            // segment hh -> K [hh*16, hh*16+16): sub-tile kh = hh>>2, col (hh&3)*32
            uint32_t base = (uint32_t)(hh >> 2) * 4096
                          + (uint32_t)rr * 128 + (uint32_t)(hh & 3) * 32;
            STS128(wfp + swz(base),      o[0], o[1], o[2], o[3]);
            STS128(wfp + swz(base + 16), o[4], o[5], o[6], o[7]);
        }

        __syncthreads();   // barrier 2: chunk-i slot reads done; Wfp visible

        // ---- prefetch chunk i+2 into slot (i&1), now fully consumed ----
        if (i + SPREF < NCHUNK) {
            issueX(i + SPREF, i & 1);
            issueW(i + SPREF, i & 1);
        }
        cpa_commit();       // commit every iter (possibly empty) -> exact ledger

        // ---- A fragments + MMA: 8 K16-tiles ----
        #pragma unroll
        for (int kt = 0; kt < 8; kt++) {
            uint32_t afr[4];
            int sub = kt >> 2;
            int row = mr * 16 + ((t & 1) << 3) + (lane & 7);
            int cb  = (kt & 3) * 32 + ((t >> 1) << 4);
            ldsm4(afr, wfp + sub * 4096 + swz(row * 128 + cb));
            #pragma unroll
            for (int nt = 0; nt < 2; nt++)
                mma16816(acc[nt], afr, bfr[kt][nt * 2], bfr[kt][nt * 2 + 1]);
        }
    }

    // ---- epilogue ----
    const int o0 = row0 + mr * 16 + (lane >> 2);
    float b0 = g_badd[o0], b8 = g_badd[o0 + 8];
    #pragma unroll
    for (int nt = 0; nt < 2; nt++) {
        int bc = nc * 16 + nt * 8 + (lane & 3) * 2;
        out[(size_t)bc * OUTF + o0]           = acc[nt][0] + b0;
        out[(size_t)(bc + 1) * OUTF + o0]     = acc[nt][1] + b0;
        out[(size_t)bc * OUTF + o0 + 8]       = acc[nt][2] + b8;
        out[(size_t)(bc + 1) * OUTF + o0 + 8] = acc[nt][3] + b8;
    }
}

__global__ void __launch_bounds__(256, 2)
gemm_kernel(const void* __restrict__ Wv, float* __restrict__ out) {
    const int* wi = (const int*)Wv;           // uniform dtype check on 256B of W
    bool i32 = true;
    #pragma unroll 8
    for (int i = 0; i < 64; i++) { int q = wi[i]; i32 &= (q >= -127 && q <= 127); }
    if (i32) gemm_body<1>((const char*)Wv, out);
    else     gemm_body<0>((const char*)Wv, out);
}

// ---------------- launch ----------------
extern "C" void kernel_launch(void* const* d_in, const int* in_sizes, int n_in,
                              void* d_out, int out_size) {
    const void* x = nullptr; const void* wq = nullptr; const void* scale = nullptr;
    const void* bias = nullptr; const void* wres = nullptr;
    for (int i = 0; i < n_in; i++) {
        long long n = in_sizes[i];
        if (n == (long long)BATCH * INF)     x = d_in[i];
        else if (n == (long long)OUTF * INF) wq = d_in[i];
        else if (n == (long long)OUTF * NG)  scale = d_in[i];
        else if (n == OUTF) { if (!bias) bias = d_in[i]; else wres = d_in[i]; }
    }
    if (!x || !wq || !scale || !bias || !wres) {
        if (n_in >= 5) {
            x = d_in[0]; wq = d_in[1]; scale = d_in[2]; bias = d_in[3]; wres = d_in[4];
        } else return;
    }
    float* out = (float*)d_out;

    prolog_kernel<<<512, 256>>>((const float*)x, scale, bias, wres);

    (void)cudaFuncSetAttribute(gemm_kernel,
                               cudaFuncAttributeMaxDynamicSharedMemorySize, SMEM_GEMM);
    gemm_kernel<<<NBLK, 256, SMEM_GEMM>>>(wq, out);
}

// round 13
// speedup vs baseline: 1.1856x; 1.1128x over previous
#include <cuda_runtime.h>
#include <cuda_fp16.h>
#include <cstdint>

// ---------------- problem constants ----------------
#define OUTF  11008
#define INF   4096
#define BATCH 64
#define NG    32              // 4096/128 quant groups
#define MTILE 32              // weight rows per CTA
#define KC    128             // K per chunk == one quant group
#define NCHUNK 32
#define NBLK  (OUTF / MTILE)  // 344 CTAs

#define SPREF 2               // prefetch distance; wait_group(1)
#define WROW  528             // padded raw int32 W row stride (conflict-free)

// smem from 1KB-aligned base:
//   SC:  2KB scales | X: 2 x 16KB | WR: 2 x 16896 | WFP: 2 x 8KB
// Reduction buffer (epilogue only) overlays X/WR: 8 blocks x 32 rows x 144B
#define SC_OFF  0
#define X_OFF   2048
#define WR_OFF  (X_OFF + 2 * 16384)          // 34816
#define WF_OFF  (WR_OFF + 2 * (MTILE * WROW))// 68608
#define SMEM_GEMM (WF_OFF + 2 * 8192 + 1024) // 86016 (x2 CTAs = 172KB < 227KB)
#define RED_BLK 4608                          // 32 rows x 144B

// ---------------- device globals ----------------
__device__ __half2 g_x16[BATCH * INF / 2];
__device__ __half  g_sc16[OUTF * NG];
__device__ float   g_badd[OUTF];

// ---------------- helpers ----------------
static __device__ __forceinline__ uint32_t smem_u32(const void* p) {
    uint32_t a;
    asm("{ .reg .u64 t; cvta.to.shared.u64 t, %1; cvt.u32.u64 %0, t; }" : "=r"(a) : "l"(p));
    return a;
}
static __device__ __forceinline__ uint32_t swz(uint32_t off) {
    return off ^ ((off >> 3) & 0x70);
}
static __device__ __forceinline__ void cpa16(uint32_t dst, const void* src) {
    asm volatile("cp.async.cg.shared.global [%0], [%1], 16;" :: "r"(dst), "l"(src));
}
static __device__ __forceinline__ void cpa_commit() {
    asm volatile("cp.async.commit_group;" ::: "memory");
}
static __device__ __forceinline__ void ldsm4(uint32_t* r, uint32_t addr) {
    asm volatile("ldmatrix.sync.aligned.m8n8.x4.shared.b16 {%0,%1,%2,%3}, [%4];"
        : "=r"(r[0]), "=r"(r[1]), "=r"(r[2]), "=r"(r[3]) : "r"(addr));
}
static __device__ __forceinline__ void mma16816(float* d, const uint32_t* a,
                                                uint32_t b0, uint32_t b1) {
    asm volatile("mma.sync.aligned.m16n8k16.row.col.f32.f16.f16.f32 "
        "{%0,%1,%2,%3}, {%4,%5,%6,%7}, {%8,%9}, {%0,%1,%2,%3};"
        : "+f"(d[0]), "+f"(d[1]), "+f"(d[2]), "+f"(d[3])
        : "r"(a[0]), "r"(a[1]), "r"(a[2]), "r"(a[3]), "r"(b0), "r"(b1));
}
static __device__ __forceinline__ __half2 u32_as_h2(uint32_t u) {
    __half2 h; *reinterpret_cast<uint32_t*>(&h) = u; return h;
}
static __device__ __forceinline__ uint32_t h2_as_u32(__half2 h) {
    return *reinterpret_cast<uint32_t*>(&h);
}

#define LDS128(r0, r1, r2, r3, addr) \
    asm volatile("ld.shared.v4.u32 {%0, %1, %2, %3}, [%4];" \
        : "=r"(r0), "=r"(r1), "=r"(r2), "=r"(r3) : "r"(addr))
#define LDS128F(f0, f1, f2, f3, addr) \
    asm volatile("ld.shared.v4.f32 {%0, %1, %2, %3}, [%4];" \
        : "=f"(f0), "=f"(f1), "=f"(f2), "=f"(f3) : "r"(addr))
#define STS128(addr, r0, r1, r2, r3) \
    asm volatile("st.shared.v4.b32 [%0], {%1, %2, %3, %4};" \
        :: "r"(addr), "r"(r0), "r"(r1), "r"(r2), "r"(r3) : "memory")
#define STSF2(addr, f0, f1) \
    asm volatile("st.shared.v2.f32 [%0], {%1, %2};" \
        :: "r"(addr), "f"(f0), "f"(f1) : "memory")

// 4 int8 bytes (packed u32) -> 2 half2, times s2 (exact PRMT 0x6400 trick)
static __device__ __forceinline__ void dq4(uint32_t packed, __half2 s2, __half2 c1152,
                                           uint32_t& o0, uint32_t& o1) {
    uint32_t v  = packed ^ 0x80808080u;
    uint32_t lo = __byte_perm(v, 0x64646464u, 0x4140);
    uint32_t hi = __byte_perm(v, 0x64646464u, 0x4342);
    o0 = h2_as_u32(__hmul2(__hsub2(u32_as_h2(lo), c1152), s2));
    o1 = h2_as_u32(__hmul2(__hsub2(u32_as_h2(hi), c1152), s2));
}

static __device__ __forceinline__ float read_mode16(const void* p, int i, int mode) {
    if (mode == 1) {
        unsigned short u = reinterpret_cast<const unsigned short*>(p)[i];
        return __uint_as_float(((unsigned)u) << 16);
    } else if (mode == 0) {
        return __half2float(reinterpret_cast<const __half*>(p)[i]);
    }
    return reinterpret_cast<const float*>(p)[i];
}

// ---------------- fused prolog: x->fp16, scale->fp16, bias+res->f32 ----------------
__global__ void prolog_kernel(const float* __restrict__ x,
                              const void* __restrict__ s,
                              const void* __restrict__ b,
                              const void* __restrict__ r) {
    const int idx = blockIdx.x * 256 + threadIdx.x;   // 512*256 = 131072

    float2 v = reinterpret_cast<const float2*>(x)[idx];
    g_x16[idx] = __floats2half2_rn(v.x, v.y);

    bool bf = true, fh = true;
    const unsigned* su = (const unsigned*)s;
    #pragma unroll 8
    for (int i = 0; i < 64; i++) {
        unsigned w = su[i];
        #pragma unroll
        for (int h = 0; h < 2; h++) {
            unsigned u = (h ? (w >> 16) : w) & 0xFFFFu;
            float ab = __uint_as_float(u << 16);
            float af = __half2float(__ushort_as_half((unsigned short)u));
            bf &= (ab > 5e-5f && ab < 0.02f);
            fh &= (af > 5e-5f && af < 0.02f);
        }
    }
    const int m = bf ? 1 : (fh ? 0 : 2);

    for (int i = idx; i < OUTF * NG; i += 512 * 256)
        g_sc16[i] = __float2half(read_mode16(s, i, m));
    if (idx < OUTF)
        g_badd[idx] = read_mode16(b, idx, m) + read_mode16(r, idx, m);
}

// ---------------- unified GEMM body (WMODE: 1 = int32 weights, 0 = int8) --------
// Warp layout: kh = wid & 3 (K-quarter), nc = wid >> 2 (32-col half).
// Each warp: 32 rows x 32 cols x K32 private accumulators; K-reduced at end.
template <int WMODE>
static __device__ __forceinline__ void gemm_body(const char* __restrict__ Wb,
                                                 float* __restrict__ out) {
    extern __shared__ char smem_raw[];
    uint32_t sb = (smem_u32(smem_raw) + 1023) & ~1023u;
    const int tid = threadIdx.x, lane = tid & 31, wid = tid >> 5;
    const int kh = wid & 3, nc = wid >> 2;
    const int t = lane >> 3;
    const int row0 = blockIdx.x * MTILE;
    const char* xb = (const char*)g_x16;
    const uint32_t SC = sb, X0 = sb + X_OFF, WR = sb + WR_OFF, WFP = sb + WF_OFF;

    auto issueX = [&](int p, int slot) {
        uint32_t xsl = X0 + slot * 16384;
        const int k0b = p * KC * 2;
        #pragma unroll
        for (int j = 0; j < 4; j++) {          // 1024 x 16B
            int c = tid + j * 256;
            int sub = c >> 9, r = (c >> 3) & 63, q = c & 7;
            cpa16(xsl + sub * 8192 + swz(r * 128 + q * 16),
                  xb + (size_t)r * (INF * 2) + k0b + sub * 128 + q * 16);
        }
    };
    auto issueW = [&](int p, int slot) {
        uint32_t wsl = WR + slot * (MTILE * WROW);
        const int k0 = p * KC;
        if (WMODE) {
            #pragma unroll
            for (int j = 0; j < 4; j++) {      // 1024 x 16B = 16KB
                int c = tid + j * 256, r = c >> 5, q = c & 31;
                cpa16(wsl + r * WROW + q * 16,
                      Wb + ((size_t)(row0 + r) * INF + k0 + q * 4) * 4);
            }
        } else {                                // 256 x 16B = 4KB
            int r = tid >> 3, q = tid & 7;
            cpa16(wsl + r * WROW + q * 16,
                  Wb + (size_t)(row0 + r) * INF + k0 + q * 16);
        }
    };

    {   // prologue: scales + chunks 0,1
        const char* scb = (const char*)g_sc16 + (size_t)row0 * NG * 2;
        if (tid < 128) cpa16(SC + tid * 16, scb + tid * 16);
        issueX(0, 0); issueW(0, 0); cpa_commit();
        issueX(1, 1); issueW(1, 1); cpa_commit();
    }

    const __half2 c1152 = __half2half2(__ushort_as_half((unsigned short)0x6480));
    float acc[2][4][4] = {};                   // mt(16-row) x nt(8-col) x frag
    const int rr = tid & 31, hh = tid >> 5;

    // warp's K-quarter: sub-tile (128B) index and byte base within it
    const int sub  = kh >> 1;
    const int khb  = (kh & 1) * 64;

    for (int i = 0; i < NCHUNK; i++) {
        asm volatile("cp.async.wait_group 1;" ::: "memory");
        __syncthreads();                        // barrier 1: chunk i visible

        const uint32_t xsl = X0 + (i & 1) * 16384;
        const uint32_t wsl = WR + (i & 1) * (MTILE * WROW);
        const uint32_t wfp = WFP + (i & 1) * 8192;

        // ---- B fragments: warp's 32 cols x K32 (np x kt = 4 ldsm4) ----
        uint32_t bfr[2][2][4];
        #pragma unroll
        for (int np = 0; np < 2; np++)
            #pragma unroll
            for (int kt = 0; kt < 2; kt++) {
                int n  = nc * 32 + np * 16 + ((t >> 1) << 3) + (lane & 7);
                int cb = khb + kt * 32 + ((t & 1) << 4);
                ldsm4(bfr[np][kt], xsl + sub * 8192 + swz(n * 128 + cb));
            }

        // ---- dequant raw W -> Wfp (16 fp16 per thread; cooperative) ----
        {
            unsigned short sv;                 // group g == i
            asm volatile("ld.shared.u16 %0, [%1];" : "=h"(sv)
                : "r"(SC + (uint32_t)(rr * NG + i) * 2) : "memory");
            __half2 s2 = __half2half2(__ushort_as_half(sv));
            uint32_t o[8];
            if (WMODE) {
                #pragma unroll
                for (int k = 0; k < 4; k++) {
                    uint32_t a0, a1, a2, a3;
                    LDS128(a0, a1, a2, a3, wsl + rr * WROW + hh * 64 + k * 16);
                    uint32_t t01 = __byte_perm(a0, a1, 0x0040);
                    uint32_t t23 = __byte_perm(a2, a3, 0x0040);
                    dq4(__byte_perm(t01, t23, 0x5410), s2, c1152, o[2*k], o[2*k+1]);
                }
            } else {
                uint32_t a0, a1, a2, a3;
                LDS128(a0, a1, a2, a3, wsl + rr * WROW + hh * 16);
                dq4(a0, s2, c1152, o[0], o[1]);
                dq4(a1, s2, c1152, o[2], o[3]);
                dq4(a2, s2, c1152, o[4], o[5]);
                dq4(a3, s2, c1152, o[6], o[7]);
            }
            uint32_t base = (uint32_t)(hh >> 2) * 4096
                          + (uint32_t)rr * 128 + (uint32_t)(hh & 3) * 32;
            STS128(wfp + swz(base),      o[0], o[1], o[2], o[3]);
            STS128(wfp + swz(base + 16), o[4], o[5], o[6], o[7]);
        }

        __syncthreads();   // barrier 2: chunk-i slot reads done; Wfp visible

        if (i + SPREF < NCHUNK) {
            issueX(i + SPREF, i & 1);
            issueW(i + SPREF, i & 1);
        }
        cpa_commit();

        // ---- A fragments (warp's K-quarter only) + MMA ----
        #pragma unroll
        for (int kt = 0; kt < 2; kt++)
            #pragma unroll
            for (int mt = 0; mt < 2; mt++) {
                uint32_t afr[4];
                int row = mt * 16 + ((t & 1) << 3) + (lane & 7);
                int cb  = khb + kt * 32 + ((t >> 1) << 4);
                ldsm4(afr, wfp + sub * 4096 + swz(row * 128 + cb));
                #pragma unroll
                for (int nt = 0; nt < 4; nt++)
                    mma16816(acc[mt][nt], afr,
                             bfr[nt >> 1][kt][(nt & 1) * 2],
                             bfr[nt >> 1][kt][(nt & 1) * 2 + 1]);
            }
    }

    // ---- epilogue: K-quarter reduction through smem, then +bias, STG ----
    __syncthreads();   // all slot reads done; overlay X/WR with reduction buffer
    {
        uint32_t rbase = X0 + (uint32_t)(kh * 2 + nc) * RED_BLK;
        #pragma unroll
        for (int mt = 0; mt < 2; mt++)
            #pragma unroll
            for (int nt = 0; nt < 4; nt++) {
                int r = mt * 16 + (lane >> 2);
                int c = nt * 8 + (lane & 3) * 2;
                STSF2(rbase + r * 144 + c * 4,       acc[mt][nt][0], acc[mt][nt][1]);
                STSF2(rbase + (r + 8) * 144 + c * 4, acc[mt][nt][2], acc[mt][nt][3]);
            }
    }
    __syncthreads();
    {
        const int r = tid & 31, g = tid >> 5;
        const int ncg = g >> 2, c0 = (g & 3) * 8;
        float v0 = 0, v1 = 0, v2 = 0, v3 = 0, v4 = 0, v5 = 0, v6 = 0, v7 = 0;
        #pragma unroll
        for (int k = 0; k < 4; k++) {
            uint32_t a = X0 + (uint32_t)(k * 2 + ncg) * RED_BLK + r * 144 + c0 * 4;
            float f0, f1, f2, f3;
            LDS128F(f0, f1, f2, f3, a);
            v0 += f0; v1 += f1; v2 += f2; v3 += f3;
            LDS128F(f0, f1, f2, f3, a + 16);
            v4 += f0; v5 += f1; v6 += f2; v7 += f3;
        }
        const int o = row0 + r;
        const float b = g_badd[o];
        const int cg = ncg * 32 + c0;
        out[(size_t)(cg + 0) * OUTF + o] = v0 + b;
        out[(size_t)(cg + 1) * OUTF + o] = v1 + b;
        out[(size_t)(cg + 2) * OUTF + o] = v2 + b;
        out[(size_t)(cg + 3) * OUTF + o] = v3 + b;
        out[(size_t)(cg + 4) * OUTF + o] = v4 + b;
        out[(size_t)(cg + 5) * OUTF + o] = v5 + b;
        out[(size_t)(cg + 6) * OUTF + o] = v6 + b;
        out[(size_t)(cg + 7) * OUTF + o] = v7 + b;
    }
}

__global__ void __launch_bounds__(256, 2)
gemm_kernel(const void* __restrict__ Wv, float* __restrict__ out) {
    const int* wi = (const int*)Wv;           // uniform dtype check on 256B of W
    bool i32 = true;
    #pragma unroll 8
    for (int i = 0; i < 64; i++) { int q = wi[i]; i32 &= (q >= -127 && q <= 127); }
    if (i32) gemm_body<1>((const char*)Wv, out);
    else     gemm_body<0>((const char*)Wv, out);
}

// ---------------- launch ----------------
extern "C" void kernel_launch(void* const* d_in, const int* in_sizes, int n_in,
                              void* d_out, int out_size) {
    const void* x = nullptr; const void* wq = nullptr; const void* scale = nullptr;
    const void* bias = nullptr; const void* wres = nullptr;
    for (int i = 0; i < n_in; i++) {
        long long n = in_sizes[i];
        if (n == (long long)BATCH * INF)     x = d_in[i];
        else if (n == (long long)OUTF * INF) wq = d_in[i];
        else if (n == (long long)OUTF * NG)  scale = d_in[i];
        else if (n == OUTF) { if (!bias) bias = d_in[i]; else wres = d_in[i]; }
    }
    if (!x || !wq || !scale || !bias || !wres) {
        if (n_in >= 5) {
            x = d_in[0]; wq = d_in[1]; scale = d_in[2]; bias = d_in[3]; wres = d_in[4];
        } else return;
    }
    float* out = (float*)d_out;

    prolog_kernel<<<512, 256>>>((const float*)x, scale, bias, wres);

    (void)cudaFuncSetAttribute(gemm_kernel,
                               cudaFuncAttributeMaxDynamicSharedMemorySize, SMEM_GEMM);
    gemm_kernel<<<NBLK, 256, SMEM_GEMM>>>(wq, out);
}

// round 14
// speedup vs baseline: 1.3060x; 1.1015x over previous
#include <cuda_runtime.h>
#include <cuda_fp16.h>
#include <cstdint>

// ---------------- problem constants ----------------
#define OUTF  11008
#define INF   4096
#define BATCH 64
#define NG    32              // 4096/128 quant groups
#define MTILE 32              // weight rows per CTA
#define KC    128             // K per chunk == one quant group
#define NCHUNK 16             // chunks per CTA (split-K = 2)
#define NBLK  ((OUTF / MTILE) * 2)   // 688 CTAs

#define SPREF 2               // prefetch distance; wait_group(1)
#define WROW  528             // padded raw int32 W row stride (conflict-free)

// smem from 1KB-aligned base:
//   SC:  2KB scales | X: 2 x 16KB | WR: 2 x 16896 | WFP: 2 x 8KB
// Reduction buffer (epilogue only) overlays X/WR: 8 blocks x 32 rows x 144B
#define SC_OFF  0
#define X_OFF   2048
#define WR_OFF  (X_OFF + 2 * 16384)          // 34816
#define WF_OFF  (WR_OFF + 2 * (MTILE * WROW))// 68608
#define SMEM_GEMM (WF_OFF + 2 * 8192 + 1024) // 86016 (x2 CTAs = 172KB < 227KB)
#define RED_BLK 4608                          // 32 rows x 144B

// ---------------- device globals ----------------
__device__ __half2 g_x16[BATCH * INF / 2];
__device__ __half  g_sc16[OUTF * NG];

// ---------------- helpers ----------------
static __device__ __forceinline__ uint32_t smem_u32(const void* p) {
    uint32_t a;
    asm("{ .reg .u64 t; cvta.to.shared.u64 t, %1; cvt.u32.u64 %0, t; }" : "=r"(a) : "l"(p));
    return a;
}
static __device__ __forceinline__ uint32_t swz(uint32_t off) {
    return off ^ ((off >> 3) & 0x70);
}
static __device__ __forceinline__ void cpa16(uint32_t dst, const void* src) {
    asm volatile("cp.async.cg.shared.global [%0], [%1], 16;" :: "r"(dst), "l"(src));
}
static __device__ __forceinline__ void cpa_commit() {
    asm volatile("cp.async.commit_group;" ::: "memory");
}
static __device__ __forceinline__ void ldsm4(uint32_t* r, uint32_t addr) {
    asm volatile("ldmatrix.sync.aligned.m8n8.x4.shared.b16 {%0,%1,%2,%3}, [%4];"
        : "=r"(r[0]), "=r"(r[1]), "=r"(r[2]), "=r"(r[3]) : "r"(addr));
}
static __device__ __forceinline__ void mma16816(float* d, const uint32_t* a,
                                                uint32_t b0, uint32_t b1) {
    asm volatile("mma.sync.aligned.m16n8k16.row.col.f32.f16.f16.f32 "
        "{%0,%1,%2,%3}, {%4,%5,%6,%7}, {%8,%9}, {%0,%1,%2,%3};"
        : "+f"(d[0]), "+f"(d[1]), "+f"(d[2]), "+f"(d[3])
        : "r"(a[0]), "r"(a[1]), "r"(a[2]), "r"(a[3]), "r"(b0), "r"(b1));
}
static __device__ __forceinline__ __half2 u32_as_h2(uint32_t u) {
    __half2 h; *reinterpret_cast<uint32_t*>(&h) = u; return h;
}
static __device__ __forceinline__ uint32_t h2_as_u32(__half2 h) {
    return *reinterpret_cast<uint32_t*>(&h);
}

#define LDS128(r0, r1, r2, r3, addr) \
    asm volatile("ld.shared.v4.u32 {%0, %1, %2, %3}, [%4];" \
        : "=r"(r0), "=r"(r1), "=r"(r2), "=r"(r3) : "r"(addr))
#define LDS128F(f0, f1, f2, f3, addr) \
    asm volatile("ld.shared.v4.f32 {%0, %1, %2, %3}, [%4];" \
        : "=f"(f0), "=f"(f1), "=f"(f2), "=f"(f3) : "r"(addr))
#define STS128(addr, r0, r1, r2, r3) \
    asm volatile("st.shared.v4.b32 [%0], {%1, %2, %3, %4};" \
        :: "r"(addr), "r"(r0), "r"(r1), "r"(r2), "r"(r3) : "memory")
#define STSF2(addr, f0, f1) \
    asm volatile("st.shared.v2.f32 [%0], {%1, %2};" \
        :: "r"(addr), "f"(f0), "f"(f1) : "memory")

// 4 int8 bytes (packed u32) -> 2 half2, times s2 (exact PRMT 0x6400 trick)
static __device__ __forceinline__ void dq4(uint32_t packed, __half2 s2, __half2 c1152,
                                           uint32_t& o0, uint32_t& o1) {
    uint32_t v  = packed ^ 0x80808080u;
    uint32_t lo = __byte_perm(v, 0x64646464u, 0x4140);
    uint32_t hi = __byte_perm(v, 0x64646464u, 0x4342);
    o0 = h2_as_u32(__hmul2(__hsub2(u32_as_h2(lo), c1152), s2));
    o1 = h2_as_u32(__hmul2(__hsub2(u32_as_h2(hi), c1152), s2));
}

static __device__ __forceinline__ float read_mode16(const void* p, int i, int mode) {
    if (mode == 1) {
        unsigned short u = reinterpret_cast<const unsigned short*>(p)[i];
        return __uint_as_float(((unsigned)u) << 16);
    } else if (mode == 0) {
        return __half2float(reinterpret_cast<const __half*>(p)[i]);
    }
    return reinterpret_cast<const float*>(p)[i];
}

// ---------------- fused prolog: x->fp16, scale->fp16, out <- bias+residual ------
__global__ void prolog_kernel(const float* __restrict__ x,
                              const void* __restrict__ s,
                              const void* __restrict__ b,
                              const void* __restrict__ r,
                              float* __restrict__ out) {
    const int idx = blockIdx.x * 256 + threadIdx.x;   // 512*256 = 131072

    float2 v = reinterpret_cast<const float2*>(x)[idx];
    g_x16[idx] = __floats2half2_rn(v.x, v.y);

    // per-block scale dtype detection (256B, L2-resident after first block)
    bool bf = true, fh = true;
    const unsigned* su = (const unsigned*)s;
    #pragma unroll 8
    for (int i = 0; i < 64; i++) {
        unsigned w = su[i];
        #pragma unroll
        for (int h = 0; h < 2; h++) {
            unsigned u = (h ? (w >> 16) : w) & 0xFFFFu;
            float ab = __uint_as_float(u << 16);
            float af = __half2float(__ushort_as_half((unsigned short)u));
            bf &= (ab > 5e-5f && ab < 0.02f);
            fh &= (af > 5e-5f && af < 0.02f);
        }
    }
    const int m = bf ? 1 : (fh ? 0 : 2);

    for (int i = idx; i < OUTF * NG; i += 512 * 256)
        g_sc16[i] = __float2half(read_mode16(s, i, m));

    // pre-fill out with bias + residual (GEMM epilogue atomically accumulates)
    for (int j = idx; j < BATCH * OUTF; j += 512 * 256) {
        int o = j % OUTF;
        out[j] = read_mode16(b, o, m) + read_mode16(r, o, m);
    }
}

// ---------------- unified GEMM body (WMODE: 1 = int32 weights, 0 = int8) --------
// CTA: tile = bid>>1 (32 rows), K-half = bid&1 (16 chunks).
// Warps: kh = wid&3 (K-quarter of chunk), nc = wid>>2 (32-col half).
template <int WMODE>
static __device__ __forceinline__ void gemm_body(const char* __restrict__ Wb,
                                                 float* __restrict__ out) {
    extern __shared__ char smem_raw[];
    uint32_t sb = (smem_u32(smem_raw) + 1023) & ~1023u;
    const int tid = threadIdx.x, lane = tid & 31, wid = tid >> 5;
    const int kh = wid & 3, nc = wid >> 2;
    const int t = lane >> 3;
    const int row0 = (blockIdx.x >> 1) * MTILE;
    const int kc0  = (blockIdx.x & 1) * NCHUNK;      // chunk offset of this K-half
    const char* xb = (const char*)g_x16;
    const uint32_t SC = sb, X0 = sb + X_OFF, WR = sb + WR_OFF, WFP = sb + WF_OFF;

    auto issueX = [&](int p, int slot) {             // p = global chunk index
        uint32_t xsl = X0 + slot * 16384;
        const int k0b = p * KC * 2;
        #pragma unroll
        for (int j = 0; j < 4; j++) {                // 1024 x 16B
            int c = tid + j * 256;
            int sub = c >> 9, r = (c >> 3) & 63, q = c & 7;
            cpa16(xsl + sub * 8192 + swz(r * 128 + q * 16),
                  xb + (size_t)r * (INF * 2) + k0b + sub * 128 + q * 16);
        }
    };
    auto issueW = [&](int p, int slot) {
        uint32_t wsl = WR + slot * (MTILE * WROW);
        const int k0 = p * KC;
        if (WMODE) {
            #pragma unroll
            for (int j = 0; j < 4; j++) {            // 1024 x 16B = 16KB
                int c = tid + j * 256, r = c >> 5, q = c & 31;
                cpa16(wsl + r * WROW + q * 16,
                      Wb + ((size_t)(row0 + r) * INF + k0 + q * 4) * 4);
            }
        } else {                                      // 256 x 16B = 4KB
            int r = tid >> 3, q = tid & 7;
            cpa16(wsl + r * WROW + q * 16,
                  Wb + (size_t)(row0 + r) * INF + k0 + q * 16);
        }
    };

    {   // prologue: scales + first two chunks of this K-half
        const char* scb = (const char*)g_sc16 + (size_t)row0 * NG * 2;
        if (tid < 128) cpa16(SC + tid * 16, scb + tid * 16);
        issueX(kc0 + 0, 0); issueW(kc0 + 0, 0); cpa_commit();
        issueX(kc0 + 1, 1); issueW(kc0 + 1, 1); cpa_commit();
    }

    const __half2 c1152 = __half2half2(__ushort_as_half((unsigned short)0x6480));
    float acc[2][4][4] = {};                   // mt(16-row) x nt(8-col) x frag
    const int rr = tid & 31, hh = tid >> 5;

    // warp's K-quarter: sub-tile (128B) index and byte base within it
    const int sub  = kh >> 1;
    const int khb  = (kh & 1) * 64;

    for (int i = 0; i < NCHUNK; i++) {
        asm volatile("cp.async.wait_group 1;" ::: "memory");
        __syncthreads();                        // barrier 1: chunk kc0+i visible

        const uint32_t xsl = X0 + (i & 1) * 16384;
        const uint32_t wsl = WR + (i & 1) * (MTILE * WROW);
        const uint32_t wfp = WFP + (i & 1) * 8192;

        // ---- B fragments: warp's 32 cols x K32 (np x kt = 4 ldsm4) ----
        uint32_t bfr[2][2][4];
        #pragma unroll
        for (int np = 0; np < 2; np++)
            #pragma unroll
            for (int kt = 0; kt < 2; kt++) {
                int n  = nc * 32 + np * 16 + ((t >> 1) << 3) + (lane & 7);
                int cb = khb + kt * 32 + ((t & 1) << 4);
                ldsm4(bfr[np][kt], xsl + sub * 8192 + swz(n * 128 + cb));
            }

        // ---- dequant raw W -> Wfp (16 fp16 per thread; cooperative) ----
        {
            unsigned short sv;                 // group index == global chunk index
            asm volatile("ld.shared.u16 %0, [%1];" : "=h"(sv)
                : "r"(SC + (uint32_t)(rr * NG + kc0 + i) * 2) : "memory");
            __half2 s2 = __half2half2(__ushort_as_half(sv));
            uint32_t o[8];
            if (WMODE) {
                #pragma unroll
                for (int k = 0; k < 4; k++) {
                    uint32_t a0, a1, a2, a3;
                    LDS128(a0, a1, a2, a3, wsl + rr * WROW + hh * 64 + k * 16);
                    uint32_t t01 = __byte_perm(a0, a1, 0x0040);
                    uint32_t t23 = __byte_perm(a2, a3, 0x0040);
                    dq4(__byte_perm(t01, t23, 0x5410), s2, c1152, o[2*k], o[2*k+1]);
                }
            } else {
                uint32_t a0, a1, a2, a3;
                LDS128(a0, a1, a2, a3, wsl + rr * WROW + hh * 16);
                dq4(a0, s2, c1152, o[0], o[1]);
                dq4(a1, s2, c1152, o[2], o[3]);
                dq4(a2, s2, c1152, o[4], o[5]);
                dq4(a3, s2, c1152, o[6], o[7]);
            }
            uint32_t base = (uint32_t)(hh >> 2) * 4096
                          + (uint32_t)rr * 128 + (uint32_t)(hh & 3) * 32;
            STS128(wfp + swz(base),      o[0], o[1], o[2], o[3]);
            STS128(wfp + swz(base + 16), o[4], o[5], o[6], o[7]);
        }

        __syncthreads();   // barrier 2: chunk-i slot reads done; Wfp visible

        if (i + SPREF < NCHUNK) {
            issueX(kc0 + i + SPREF, i & 1);
            issueW(kc0 + i + SPREF, i & 1);
        }
        cpa_commit();

        // ---- A fragments (warp's K-quarter only) + MMA ----
        #pragma unroll
        for (int kt = 0; kt < 2; kt++)
            #pragma unroll
            for (int mt = 0; mt < 2; mt++) {
                uint32_t afr[4];
                int row = mt * 16 + ((t & 1) << 3) + (lane & 7);
                int cb  = khb + kt * 32 + ((t >> 1) << 4);
                ldsm4(afr, wfp + sub * 4096 + swz(row * 128 + cb));
                #pragma unroll
                for (int nt = 0; nt < 4; nt++)
                    mma16816(acc[mt][nt], afr,
                             bfr[nt >> 1][kt][(nt & 1) * 2],
                             bfr[nt >> 1][kt][(nt & 1) * 2 + 1]);
            }
    }

    // ---- epilogue: K-quarter reduction via smem, then atomicAdd into out ----
    __syncthreads();   // all slot reads done; overlay X/WR with reduction buffer
    {
        uint32_t rbase = X0 + (uint32_t)(kh * 2 + nc) * RED_BLK;
        #pragma unroll
        for (int mt = 0; mt < 2; mt++)
            #pragma unroll
            for (int nt = 0; nt < 4; nt++) {
                int r = mt * 16 + (lane >> 2);
                int c = nt * 8 + (lane & 3) * 2;
                STSF2(rbase + r * 144 + c * 4,       acc[mt][nt][0], acc[mt][nt][1]);
                STSF2(rbase + (r + 8) * 144 + c * 4, acc[mt][nt][2], acc[mt][nt][3]);
            }
    }
    __syncthreads();
    {
        const int r = tid & 31, g = tid >> 5;
        const int ncg = g >> 2, cb0 = (g & 3) * 8;
        float v0 = 0, v1 = 0, v2 = 0, v3 = 0, v4 = 0, v5 = 0, v6 = 0, v7 = 0;
        #pragma unroll
        for (int k = 0; k < 4; k++) {
            uint32_t a = X0 + (uint32_t)(k * 2 + ncg) * RED_BLK + r * 144 + cb0 * 4;
            float f0, f1, f2, f3;
            LDS128F(f0, f1, f2, f3, a);
            v0 += f0; v1 += f1; v2 += f2; v3 += f3;
            LDS128F(f0, f1, f2, f3, a + 16);
            v4 += f0; v5 += f1; v6 += f2; v7 += f3;
        }
        const int o = row0 + r;
        const int cg = ncg * 32 + cb0;
        atomicAdd(&out[(size_t)(cg + 0) * OUTF + o], v0);
        atomicAdd(&out[(size_t)(cg + 1) * OUTF + o], v1);
        atomicAdd(&out[(size_t)(cg + 2) * OUTF + o], v2);
        atomicAdd(&out[(size_t)(cg + 3) * OUTF + o], v3);
        atomicAdd(&out[(size_t)(cg + 4) * OUTF + o], v4);
        atomicAdd(&out[(size_t)(cg + 5) * OUTF + o], v5);
        atomicAdd(&out[(size_t)(cg + 6) * OUTF + o], v6);
        atomicAdd(&out[(size_t)(cg + 7) * OUTF + o], v7);
    }
}

__global__ void __launch_bounds__(256, 2)
gemm_kernel(const void* __restrict__ Wv, float* __restrict__ out) {
    const int* wi = (const int*)Wv;           // uniform dtype check on 256B of W
    bool i32 = true;
    #pragma unroll 8
    for (int i = 0; i < 64; i++) { int q = wi[i]; i32 &= (q >= -127 && q <= 127); }
    if (i32) gemm_body<1>((const char*)Wv, out);
    else     gemm_body<0>((const char*)Wv, out);
}

// ---------------- launch ----------------
extern "C" void kernel_launch(void* const* d_in, const int* in_sizes, int n_in,
                              void* d_out, int out_size) {
    const void* x = nullptr; const void* wq = nullptr; const void* scale = nullptr;
    const void* bias = nullptr; const void* wres = nullptr;
    for (int i = 0; i < n_in; i++) {
        long long n = in_sizes[i];
        if (n == (long long)BATCH * INF)     x = d_in[i];
        else if (n == (long long)OUTF * INF) wq = d_in[i];
        else if (n == (long long)OUTF * NG)  scale = d_in[i];
        else if (n == OUTF) { if (!bias) bias = d_in[i]; else wres = d_in[i]; }
    }
    if (!x || !wq || !scale || !bias || !wres) {
        if (n_in >= 5) {
            x = d_in[0]; wq = d_in[1]; scale = d_in[2]; bias = d_in[3]; wres = d_in[4];
        } else return;
    }
    float* out = (float*)d_out;

    prolog_kernel<<<512, 256>>>((const float*)x, scale, bias, wres, out);

    (void)cudaFuncSetAttribute(gemm_kernel,
                               cudaFuncAttributeMaxDynamicSharedMemorySize, SMEM_GEMM);
    gemm_kernel<<<NBLK, 256, SMEM_GEMM>>>(wq, out);
}